// round 2
// baseline (speedup 1.0000x reference)
#include <cuda_runtime.h>
#include <cuda.h>
#include <cuda_fp16.h>
#include <cstdint>

// ---------------- problem constants ----------------
#define NNODES 16384
#define DIM    128
#define KC     32                          // K per chunk
#define CHUNKS (NNODES / KC)               // 512
#define STAGES 5

// B (zh) padded chunk layout: [chunk][o:128][40 halves] (32 data + 8 pad, 80B rows)
#define BROW_H   40
#define BCHUNK_H (DIM * BROW_H)            // 5120 halves = 10240 B
#define BCHUNK_B (BCHUNK_H * 2)

#define A32_BYTES (128 * KC * 4)           // 16384 B per stage
#define A16_ROWB  80                       // padded fp16 A row stride (conflict-free ldmatrix)
#define A16_BYTES (128 * A16_ROWB)         // 10240 B per buffer
#define TXB (A32_BYTES + BCHUNK_B)         // 26624

// smem layout (gemm kernel)
#define SM_MBAR 0
#define SM_A32  1024
#define SM_B    (1024 + STAGES * A32_BYTES)              // 82944
#define SM_A16  (SM_B + STAGES * BCHUNK_B)               // 134144
#define GEMM_SMEM (SM_A16 + 2 * A16_BYTES)               // 154624

// scratch (__device__ globals: allocation-free rule)
__device__ __half g_zh[CHUNKS * BCHUNK_H];   // 5 MB, padded-chunk layout
__device__ float  g_u [NNODES * DIM];        // 8 MB: x@W1^T + b

// ---------------- PTX helpers (all compute_103-baseline) ----------------
__device__ __forceinline__ uint32_t smem_u32(const void* p) {
    uint32_t a;
    asm("{ .reg .u64 t; cvta.to.shared.u64 t, %1; cvt.u32.u64 %0, t; }" : "=r"(a) : "l"(p));
    return a;
}
__device__ __forceinline__ void mbar_init(uint32_t mbar, uint32_t cnt) {
    asm volatile("mbarrier.init.shared.b64 [%0], %1;" :: "r"(mbar), "r"(cnt) : "memory");
}
__device__ __forceinline__ void mbar_expect_tx(uint32_t mbar, uint32_t bytes) {
    asm volatile("mbarrier.arrive.expect_tx.shared.b64 _, [%0], %1;" :: "r"(mbar), "r"(bytes) : "memory");
}
__device__ __forceinline__ void mbar_wait(uint32_t mbar, uint32_t parity) {
    asm volatile(
        "{\n\t.reg .pred P;\n\t"
        "W_%=:\n\t"
        "mbarrier.try_wait.parity.shared.b64 P, [%0], %1, 0x989680;\n\t"
        "@P bra D_%=;\n\t"
        "bra W_%=;\n\t"
        "D_%=:\n\t}"
        :: "r"(mbar), "r"(parity) : "memory");
}
__device__ __forceinline__ void tma_2d(uint32_t dst, const CUtensorMap* map,
                                       int cx, int cy, uint32_t mbar) {
    asm volatile(
        "cp.async.bulk.tensor.2d.shared::cta.global.tile.mbarrier::complete_tx::bytes "
        "[%0], [%1, {%2, %3}], [%4];"
        :: "r"(dst), "l"(map), "r"(cx), "r"(cy), "r"(mbar) : "memory");
}
__device__ __forceinline__ void bulk_cp(uint32_t dst, const void* src, uint32_t bytes, uint32_t mbar) {
    asm volatile(
        "cp.async.bulk.shared::cta.global.mbarrier::complete_tx::bytes [%0], [%1], %2, [%3];"
        :: "r"(dst), "l"(src), "r"(bytes), "r"(mbar) : "memory");
}
__device__ __forceinline__ void ldm_x4(uint32_t* r, uint32_t addr) {
    asm volatile("ldmatrix.sync.aligned.m8n8.x4.shared.b16 {%0,%1,%2,%3}, [%4];"
        : "=r"(r[0]), "=r"(r[1]), "=r"(r[2]), "=r"(r[3]) : "r"(addr));
}
__device__ __forceinline__ void mma16816(float* c, const uint32_t* a, const uint32_t* b) {
    asm volatile("mma.sync.aligned.m16n8k16.row.col.f32.f16.f16.f32 "
        "{%0,%1,%2,%3}, {%4,%5,%6,%7}, {%8,%9}, {%0,%1,%2,%3};"
        : "+f"(c[0]), "+f"(c[1]), "+f"(c[2]), "+f"(c[3])
        : "r"(a[0]), "r"(a[1]), "r"(a[2]), "r"(a[3]), "r"(b[0]), "r"(b[1]));
}

// ============================================================================
// Kernel 1 (prep): 128 CTAs x 512 threads, 128 nodes/CTA, single wave.
//   z[m][o] = sum_d x[m][d] * W[o][128+d]  -> fp16, padded chunk layout g_zh
//   u[m][o] = sum_d x[m][d] * W[o][d] + b[o] -> fp32 g_u
// ============================================================================
#define PREP_SMEM ((128 * DIM + 256 * 129) * 4 + 128 * 128 * 2)   // 230400

__global__ __launch_bounds__(512) void prep_kernel(const float* __restrict__ x,
                                                   const float* __restrict__ W,
                                                   const float* __restrict__ b) {
    extern __shared__ float sm1[];
    float*  xs  = sm1;                              // [128][128]
    float*  ws  = sm1 + 128 * DIM;                  // [256][129]
    __half* zsm = (__half*)(sm1 + 128 * DIM + 256 * 129);  // [128 o][128 node]
    const int tid = threadIdx.x;
    const int node0 = blockIdx.x * 128;

    const float4* xg = reinterpret_cast<const float4*>(x + (size_t)node0 * DIM);
    float4* xs4 = reinterpret_cast<float4*>(xs);
    #pragma unroll
    for (int i = tid; i < 128 * DIM / 4; i += 512) xs4[i] = xg[i];

    for (int idx = tid; idx < 256 * DIM; idx += 512) {
        int j = idx >> 7, k = idx & 127;
        // rows 0..127: W2 (z weights, cols 128..255); rows 128..255: W1 (u weights)
        float v = (j < DIM) ? W[j * 256 + DIM + k] : W[(j - DIM) * 256 + k];
        ws[j * 129 + k] = v;
    }
    __syncthreads();

    const int ng = tid >> 4;   // 0..31 -> nodes 4*ng .. 4*ng+3
    const int og = tid & 15;
    float acc[64];
    #pragma unroll
    for (int i = 0; i < 64; i++) acc[i] = 0.f;

    #pragma unroll 4
    for (int k = 0; k < DIM; ++k) {
        float xv[4];
        #pragma unroll
        for (int i = 0; i < 4; i++) xv[i] = xs[(4 * ng + i) * DIM + k];
        #pragma unroll
        for (int q = 0; q < 4; q++) {
            #pragma unroll
            for (int r = 0; r < 4; r++) {
                float wv = ws[(4 * og + 64 * q + r) * 129 + k];
                #pragma unroll
                for (int i = 0; i < 4; i++)
                    acc[i * 16 + 4 * q + r] = fmaf(xv[i], wv, acc[i * 16 + 4 * q + r]);
            }
        }
    }

    float4 bq0 = *reinterpret_cast<const float4*>(b + 4 * og);
    float4 bq1 = *reinterpret_cast<const float4*>(b + 4 * og + 64);

    #pragma unroll
    for (int i = 0; i < 4; i++) {
        int mloc = 4 * ng + i;
        // z (q=0,1) -> zsm[o][node] fp16
        #pragma unroll
        for (int q = 0; q < 2; q++)
            #pragma unroll
            for (int r = 0; r < 4; r++) {
                int j = 4 * og + 64 * q + r;
                zsm[j * 128 + mloc] = __float2half_rn(acc[i * 16 + 4 * q + r]);
            }
        // u (q=2,3) -> coalesced float4 + bias
        float4 u0, u1;
        u0.x = acc[i*16+8] + bq0.x;  u0.y = acc[i*16+9] + bq0.y;
        u0.z = acc[i*16+10] + bq0.z; u0.w = acc[i*16+11] + bq0.w;
        u1.x = acc[i*16+12] + bq1.x; u1.y = acc[i*16+13] + bq1.y;
        u1.z = acc[i*16+14] + bq1.z; u1.w = acc[i*16+15] + bq1.w;
        *reinterpret_cast<float4*>(g_u + (size_t)(node0 + mloc) * DIM + 4 * og)      = u0;
        *reinterpret_cast<float4*>(g_u + (size_t)(node0 + mloc) * DIM + 4 * og + 64) = u1;
    }
    __syncthreads();

    // coalesced write-out of zsm -> g_zh padded chunk layout
    // thread t: o = t>>2, quarter q = t&3 (nodes q*32..q*32+31 -> chunk c0+q)
    {
        int o = tid >> 2, q = tid & 3;
        int c0 = blockIdx.x * 4;
        const uint4* src = reinterpret_cast<const uint4*>(zsm + o * 128 + q * 32);
        __half* dstp = g_zh + (size_t)(c0 + q) * BCHUNK_H + o * BROW_H;
        uint4* dst = reinterpret_cast<uint4*>(dstp);
        #pragma unroll
        for (int i = 0; i < 4; i++) dst[i] = src[i];
    }
}

// ============================================================================
// Kernel 2 (main): 128 CTAs x 256 threads.
//   out[m][o] = ReLU( sum_k adj[m][k] * zh[k][o] + u[m][o] )
//   TMA fp32 adj tiles -> smem, in-SM cvt to fp16, mma.sync m16n8k16.
// ============================================================================
__global__ __launch_bounds__(256) void gemm_kernel(
    const __grid_constant__ CUtensorMap tma_a,
    float* __restrict__ out) {
    extern __shared__ char smem[];
    const uint32_t sb = smem_u32(smem);
    const uint32_t MB = sb + SM_MBAR;

    const int tid  = threadIdx.x;
    const int lane = tid & 31;
    const int w    = tid >> 5;
    const int m0g  = blockIdx.x * 128;
    const int m0w  = (w >> 2) * 64;     // warp tile 64x32
    const int n0w  = (w & 3) * 32;

    if (tid == 0) {
        #pragma unroll
        for (int s = 0; s < STAGES; ++s) mbar_init(MB + 8 * s, 1);
    }
    __syncthreads();

    if (tid == 0) {
        #pragma unroll
        for (int s = 0; s < STAGES; ++s) {
            mbar_expect_tx(MB + 8 * s, TXB);
            tma_2d(sb + SM_A32 + s * A32_BYTES, &tma_a, s * KC, m0g, MB + 8 * s);
            bulk_cp(sb + SM_B + s * BCHUNK_B, g_zh + (size_t)s * BCHUNK_H, BCHUNK_B, MB + 8 * s);
        }
    }

    // per-lane ldmatrix source offsets
    uint32_t aoff[4];
    #pragma unroll
    for (int mi = 0; mi < 4; ++mi)
        aoff[mi] = (uint32_t)((m0w + mi * 16 + (lane & 15)) * A16_ROWB + (lane >> 4) * 16);
    const int bg = lane >> 3;
    const uint32_t boff =
        (uint32_t)((n0w + ((bg >> 1) & 1) * 8 + (lane & 7)) * A16_ROWB + (bg & 1) * 16);

    // conversion mapping: thread -> (row, half)
    const int crow = tid >> 1, chalf = tid & 1;

    float acc[4][4][4];
    #pragma unroll
    for (int i = 0; i < 4; i++)
        #pragma unroll
        for (int j = 0; j < 4; j++)
            #pragma unroll
            for (int k = 0; k < 4; k++) acc[i][j][k] = 0.f;

    int s = 0, ph = 0, p = 0;
    #pragma unroll 1
    for (int it = 0; it < CHUNKS; ++it) {
        mbar_wait(MB + 8 * s, ph);

        // --- B fragments for both k-steps (reads B stage s) ---
        uint32_t bfr[2][2][4];
        const uint32_t bst = sb + SM_B + s * BCHUNK_B;
        #pragma unroll
        for (int nt2 = 0; nt2 < 2; ++nt2)
            #pragma unroll
            for (int ks = 0; ks < 2; ++ks)
                ldm_x4(bfr[nt2][ks], bst + boff + nt2 * 16 * A16_ROWB + ks * 32);

        // --- convert A32[s] -> A16[p] (fp32 -> fp16, de-swizzle + re-pad) ---
        {
            const char* a32 = smem + SM_A32 + s * A32_BYTES;
            char* a16 = smem + SM_A16 + p * A16_BYTES + crow * A16_ROWB + chalf * 32;
            const uint32_t rsw = (uint32_t)(crow & 7) << 4;
            #pragma unroll
            for (int jp = 0; jp < 2; ++jp) {
                uint32_t b0 = (uint32_t)(crow * 128 + (chalf * 4 + jp * 2) * 16);
                float4 v0 = *reinterpret_cast<const float4*>(a32 + (b0 ^ rsw));
                float4 v1 = *reinterpret_cast<const float4*>(a32 + ((b0 + 16) ^ rsw));
                __half2 h0 = __floats2half2_rn(v0.x, v0.y);
                __half2 h1 = __floats2half2_rn(v0.z, v0.w);
                __half2 h2 = __floats2half2_rn(v1.x, v1.y);
                __half2 h3 = __floats2half2_rn(v1.z, v1.w);
                uint4 pk;
                pk.x = *reinterpret_cast<uint32_t*>(&h0);
                pk.y = *reinterpret_cast<uint32_t*>(&h1);
                pk.z = *reinterpret_cast<uint32_t*>(&h2);
                pk.w = *reinterpret_cast<uint32_t*>(&h3);
                *reinterpret_cast<uint4*>(a16 + jp * 16) = pk;
            }
        }
        __syncthreads();   // A16[p] visible; A32[s] & B[s-1-consumption] quiesced

        // --- delayed refill: chunk it+STAGES-1 into stage (it+STAGES-1)%STAGES ---
        if (tid == 0 && it >= 1) {
            int nxt = it + STAGES - 1;
            if (nxt < CHUNKS) {
                int rs = nxt % STAGES;
                mbar_expect_tx(MB + 8 * rs, TXB);
                tma_2d(sb + SM_A32 + rs * A32_BYTES, &tma_a, nxt * KC, m0g, MB + 8 * rs);
                bulk_cp(sb + SM_B + rs * BCHUNK_B, g_zh + (size_t)nxt * BCHUNK_H,
                        BCHUNK_B, MB + 8 * rs);
            }
        }

        // --- A fragments + MMA (reads A16[p] only) ---
        const uint32_t a16b = sb + SM_A16 + p * A16_BYTES;
        #pragma unroll
        for (int ks = 0; ks < 2; ++ks) {
            uint32_t afr[4][4];
            #pragma unroll
            for (int mi = 0; mi < 4; ++mi)
                ldm_x4(afr[mi], a16b + aoff[mi] + ks * 32);
            #pragma unroll
            for (int mi = 0; mi < 4; ++mi)
                #pragma unroll
                for (int nt = 0; nt < 4; ++nt)
                    mma16816(acc[mi][nt], afr[mi], &bfr[nt >> 1][ks][(nt & 1) * 2]);
        }

        p ^= 1;
        if (++s == STAGES) { s = 0; ph ^= 1; }
    }

    // --- epilogue: += u, ReLU, store ---
    #pragma unroll
    for (int mi = 0; mi < 4; ++mi) {
        int r = m0w + mi * 16 + (lane >> 2);
        #pragma unroll
        for (int nt = 0; nt < 4; ++nt) {
            int c = n0w + nt * 8 + 2 * (lane & 3);
            size_t i0 = (size_t)(m0g + r) * DIM + c;
            float2 u0 = *reinterpret_cast<const float2*>(g_u + i0);
            float2 u1 = *reinterpret_cast<const float2*>(g_u + i0 + 8 * DIM);
            const float* a = acc[mi][nt];
            float2 o0, o1;
            o0.x = fmaxf(a[0] + u0.x, 0.f); o0.y = fmaxf(a[1] + u0.y, 0.f);
            o1.x = fmaxf(a[2] + u1.x, 0.f); o1.y = fmaxf(a[3] + u1.y, 0.f);
            *reinterpret_cast<float2*>(out + i0)           = o0;
            *reinterpret_cast<float2*>(out + i0 + 8 * DIM) = o1;
        }
    }
}

// ============================================================================
// Host launch
// ============================================================================
typedef CUresult (*EncodeFn)(CUtensorMap*, CUtensorMapDataType, cuuint32_t, void*,
                             const cuuint64_t*, const cuuint64_t*, const cuuint32_t*,
                             const cuuint32_t*, CUtensorMapInterleave, CUtensorMapSwizzle,
                             CUtensorMapL2promotion, CUtensorMapFloatOOBfill);

extern "C" void kernel_launch(void* const* d_in, const int* in_sizes, int n_in,
                              void* d_out, int out_size) {
    const float *x = nullptr, *adj = nullptr, *W = nullptr, *b = nullptr;
    for (int i = 0; i < n_in; ++i) {
        switch (in_sizes[i]) {
            case NNODES * DIM: x = (const float*)d_in[i]; break;
            case 32768:        W = (const float*)d_in[i]; break;
            case 128:          b = (const float*)d_in[i]; break;
            default:           adj = (const float*)d_in[i]; break;
        }
    }
    float* out = (float*)d_out;

    void* fn = nullptr;
    cudaDriverEntryPointQueryResult qr;
#if CUDART_VERSION >= 12050
    cudaGetDriverEntryPointByVersion("cuTensorMapEncodeTiled", &fn, 12000,
                                     cudaEnableDefault, &qr);
#else
    cudaGetDriverEntryPoint("cuTensorMapEncodeTiled", &fn, cudaEnableDefault, &qr);
#endif
    if (!fn) return;
    EncodeFn encode = (EncodeFn)fn;

    CUtensorMap mapA;
    {
        cuuint64_t dims[2]   = {NNODES, NNODES};
        cuuint64_t stride[1] = {NNODES * 4ull};
        cuuint32_t box[2]    = {KC, 128};          // 128B x 128 rows, SW128
        cuuint32_t es[2]     = {1, 1};
        encode(&mapA, CU_TENSOR_MAP_DATA_TYPE_FLOAT32, 2, (void*)adj, dims, stride, box, es,
               CU_TENSOR_MAP_INTERLEAVE_NONE, CU_TENSOR_MAP_SWIZZLE_128B,
               CU_TENSOR_MAP_L2_PROMOTION_L2_128B, CU_TENSOR_MAP_FLOAT_OOB_FILL_NONE);
    }

    cudaFuncSetAttribute(prep_kernel, cudaFuncAttributeMaxDynamicSharedMemorySize, PREP_SMEM);
    cudaFuncSetAttribute(gemm_kernel, cudaFuncAttributeMaxDynamicSharedMemorySize, GEMM_SMEM);

    prep_kernel<<<NNODES / 128, 512, PREP_SMEM>>>(x, W, b);
    gemm_kernel<<<NNODES / 128, 256, GEMM_SMEM>>>(mapA, out);
}